// round 4
// baseline (speedup 1.0000x reference)
#include <cuda_runtime.h>
#include <math.h>
#include <stdint.h>

#define BB   4
#define LQV  1024
#define CCV  256
#define HHV  8
#define DHV  32
#define DFFV 1024
#define LSRCV 21760
#define MQ (BB*LQV)     // 4096
#define MS (BB*LSRCV)   // 87040

// ---------------- scratch (static device globals) ---------------------------
__device__ float g_qk  [MQ*CCV];
__device__ float g_q   [MQ*CCV];
__device__ float g_k   [MQ*CCV];
__device__ float g_v   [MQ*CCV];
__device__ float g_attn[MQ*CCV];
__device__ float g_res [MQ*CCV];
__device__ float g_tgta[MQ*CCV];
__device__ float g_value[(size_t)MS*CCV];
__device__ float g_q2  [MQ*CCV];
__device__ float g_off [MQ*CCV];
__device__ float g_aw  [MQ*128];
__device__ float g_samp[MQ*CCV];
__device__ float g_tgtb[MQ*CCV];
__device__ float g_hid [MQ*DFFV];

// ---------------- elementwise add -------------------------------------------
__global__ void add_kernel(const float* __restrict__ a, const float* __restrict__ b,
                           float* __restrict__ o, int n) {
    int i = blockIdx.x * blockDim.x + threadIdx.x;
    if (i < n) o[i] = a[i] + b[i];
}

// ---------------- tf32 tensor-core GEMM -------------------------------------
// C = A(MxK) * W(NxK)^T + bias [+resid][relu]
// block tile 128x128x16, 8 warps of 64x32, double-buffered smem.
__device__ __forceinline__ uint32_t f2tf(float f) {
    uint32_t r;
    asm("cvt.rna.tf32.f32 %0, %1;" : "=r"(r) : "f"(f));
    return r;
}

#define TCS 20  // smem row stride (floats); (lane/4)*20 + lane%4 is bank-bijective

template<bool RELU, bool RESID>
__global__ __launch_bounds__(256) void gemm_tc(
    const float* __restrict__ A, const float* __restrict__ W,
    const float* __restrict__ bias, const float* __restrict__ resid,
    float* __restrict__ C, int M, int N, int K)
{
    __shared__ uint32_t As[2][128][TCS];
    __shared__ uint32_t Bs[2][128][TCS];

    const int tid  = threadIdx.x;
    const int wid  = tid >> 5;
    const int lane = tid & 31;
    const int wm = (wid & 1) * 64;
    const int wn = (wid >> 1) * 32;
    const int bm = blockIdx.y * 128;
    const int bn = blockIdx.x * 128;
    const int lrow = lane >> 2;  // 0..7
    const int lcol = lane & 3;   // 0..3

    float acc[4][4][4];
    #pragma unroll
    for (int i = 0; i < 4; ++i)
        #pragma unroll
        for (int j = 0; j < 4; ++j)
            #pragma unroll
            for (int r = 0; r < 4; ++r) acc[i][j][r] = 0.f;

    float4 ra[2], rb[2];

    #pragma unroll
    for (int u = 0; u < 2; ++u) {
        int idx = tid + u * 256;
        int m = idx >> 2, kk = (idx & 3) << 2;
        ra[u] = *(const float4*)&A[(size_t)(bm + m) * K + kk];
        rb[u] = *(const float4*)&W[(size_t)(bn + m) * K + kk];
    }
    #pragma unroll
    for (int u = 0; u < 2; ++u) {
        int idx = tid + u * 256;
        int m = idx >> 2, kk = (idx & 3) << 2;
        As[0][m][kk+0] = f2tf(ra[u].x); As[0][m][kk+1] = f2tf(ra[u].y);
        As[0][m][kk+2] = f2tf(ra[u].z); As[0][m][kk+3] = f2tf(ra[u].w);
        Bs[0][m][kk+0] = f2tf(rb[u].x); Bs[0][m][kk+1] = f2tf(rb[u].y);
        Bs[0][m][kk+2] = f2tf(rb[u].z); Bs[0][m][kk+3] = f2tf(rb[u].w);
    }
    __syncthreads();

    int cur = 0;
    for (int kt = 0; kt < K; kt += 16) {
        const bool has_next = (kt + 16) < K;
        if (has_next) {
            #pragma unroll
            for (int u = 0; u < 2; ++u) {
                int idx = tid + u * 256;
                int m = idx >> 2, kk = (idx & 3) << 2;
                ra[u] = *(const float4*)&A[(size_t)(bm + m) * K + kt + 16 + kk];
                rb[u] = *(const float4*)&W[(size_t)(bn + m) * K + kt + 16 + kk];
            }
        }

        #pragma unroll
        for (int kb = 0; kb < 16; kb += 8) {
            uint32_t af[4][4], bf[4][2];
            // PTX m16n8k8 tf32 A fragment:
            //   a0=(row,col) a1=(row+8,col) a2=(row,col+4) a3=(row+8,col+4)
            #pragma unroll
            for (int i = 0; i < 4; ++i) {
                af[i][0] = As[cur][wm + i*16 +     lrow][kb + lcol];
                af[i][1] = As[cur][wm + i*16 + 8 + lrow][kb + lcol];
                af[i][2] = As[cur][wm + i*16 +     lrow][kb + lcol + 4];
                af[i][3] = As[cur][wm + i*16 + 8 + lrow][kb + lcol + 4];
            }
            #pragma unroll
            for (int j = 0; j < 4; ++j) {
                bf[j][0] = Bs[cur][wn + j*8 + lrow][kb + lcol];
                bf[j][1] = Bs[cur][wn + j*8 + lrow][kb + lcol + 4];
            }
            #pragma unroll
            for (int i = 0; i < 4; ++i)
                #pragma unroll
                for (int j = 0; j < 4; ++j) {
                    asm volatile(
                        "mma.sync.aligned.m16n8k8.row.col.f32.tf32.tf32.f32 "
                        "{%0,%1,%2,%3},{%4,%5,%6,%7},{%8,%9},{%0,%1,%2,%3};\n"
                        : "+f"(acc[i][j][0]), "+f"(acc[i][j][1]),
                          "+f"(acc[i][j][2]), "+f"(acc[i][j][3])
                        : "r"(af[i][0]), "r"(af[i][1]), "r"(af[i][2]), "r"(af[i][3]),
                          "r"(bf[j][0]), "r"(bf[j][1]));
                }
        }

        if (has_next) {
            int nxt = cur ^ 1;
            #pragma unroll
            for (int u = 0; u < 2; ++u) {
                int idx = tid + u * 256;
                int m = idx >> 2, kk = (idx & 3) << 2;
                As[nxt][m][kk+0] = f2tf(ra[u].x); As[nxt][m][kk+1] = f2tf(ra[u].y);
                As[nxt][m][kk+2] = f2tf(ra[u].z); As[nxt][m][kk+3] = f2tf(ra[u].w);
                Bs[nxt][m][kk+0] = f2tf(rb[u].x); Bs[nxt][m][kk+1] = f2tf(rb[u].y);
                Bs[nxt][m][kk+2] = f2tf(rb[u].z); Bs[nxt][m][kk+3] = f2tf(rb[u].w);
            }
            __syncthreads();
            cur = nxt;
        }
    }

    // epilogue: c0=(row, col2) c1=(row, col2+1) c2=(row+8, col2) c3=(row+8, col2+1)
    #pragma unroll
    for (int j = 0; j < 4; ++j) {
        const int cc = bn + wn + j*8 + (lcol << 1);
        const float b0 = bias[cc], b1 = bias[cc + 1];
        #pragma unroll
        for (int i = 0; i < 4; ++i) {
            const int r0 = bm + wm + i*16 + lrow;
            float2 o0, o1;
            o0.x = acc[i][j][0] + b0; o0.y = acc[i][j][1] + b1;
            o1.x = acc[i][j][2] + b0; o1.y = acc[i][j][3] + b1;
            if (RESID) {
                float2 v0 = *(const float2*)&resid[(size_t)r0 * N + cc];
                float2 v1 = *(const float2*)&resid[(size_t)(r0+8) * N + cc];
                o0.x += v0.x; o0.y += v0.y; o1.x += v1.x; o1.y += v1.y;
            }
            if (RELU) {
                o0.x = fmaxf(o0.x, 0.f); o0.y = fmaxf(o0.y, 0.f);
                o1.x = fmaxf(o1.x, 0.f); o1.y = fmaxf(o1.y, 0.f);
            }
            *(float2*)&C[(size_t)r0 * N + cc]     = o0;
            *(float2*)&C[(size_t)(r0+8) * N + cc] = o1;
        }
    }
}

// ---------------- flash attention: warp-per-query, DH=32 --------------------
__global__ __launch_bounds__(256) void attn_kernel(
    const float* __restrict__ Q, const float* __restrict__ Kb,
    const float* __restrict__ Vb, float* __restrict__ O)
{
    __shared__ float Ks[64][33];
    __shared__ float Vs[64][33];
    __shared__ float Ps[8][64];
    const int bh = blockIdx.x;
    const int b = bh >> 3, h = bh & 7;
    const int w = threadIdx.x >> 5;
    const int lane = threadIdx.x & 31;
    const int q = blockIdx.y * 8 + w;

    const float scale = 0.17677669529663687f;
    float qv = Q[((size_t)(b*LQV + q))*CCV + h*DHV + lane] * scale;
    float qr[32];
    #pragma unroll
    for (int d = 0; d < 32; ++d) qr[d] = __shfl_sync(0xffffffffu, qv, d);

    float m = -1e30f, l = 0.f, acc = 0.f;

    for (int kt = 0; kt < LQV; kt += 64) {
        for (int i = threadIdx.x; i < 64*32; i += 256) {
            int r = i >> 5, c = i & 31;
            size_t gi = ((size_t)(b*LQV + kt + r))*CCV + h*DHV + c;
            Ks[r][c] = Kb[gi];
            Vs[r][c] = Vb[gi];
        }
        __syncthreads();

        float s0 = 0.f, s1 = 0.f;
        #pragma unroll
        for (int d = 0; d < 32; ++d) {
            s0 += qr[d] * Ks[lane][d];
            s1 += qr[d] * Ks[lane+32][d];
        }
        float tmax = fmaxf(s0, s1);
        #pragma unroll
        for (int o = 16; o > 0; o >>= 1)
            tmax = fmaxf(tmax, __shfl_xor_sync(0xffffffffu, tmax, o));
        float mn = fmaxf(m, tmax);
        float p0 = __expf(s0 - mn), p1 = __expf(s1 - mn);
        float sc = __expf(m - mn);
        float ps = p0 + p1;
        #pragma unroll
        for (int o = 16; o > 0; o >>= 1)
            ps += __shfl_xor_sync(0xffffffffu, ps, o);
        l = l * sc + ps;
        m = mn;
        Ps[w][lane] = p0; Ps[w][lane+32] = p1;
        __syncwarp();
        float a = 0.f;
        #pragma unroll
        for (int j = 0; j < 64; ++j) a += Ps[w][j] * Vs[j][lane];
        acc = acc * sc + a;
        __syncthreads();
    }
    O[((size_t)(b*LQV + q))*CCV + h*DHV + lane] = acc / l;
}

// ---------------- LayerNorm: block per row (C=256) --------------------------
__global__ __launch_bounds__(256) void ln_kernel(
    const float* __restrict__ x, const float* __restrict__ g,
    const float* __restrict__ b, float* __restrict__ y)
{
    const int row = blockIdx.x;
    const int t = threadIdx.x;
    float v = x[(size_t)row * 256 + t];
    float s = v, sq = v * v;
    #pragma unroll
    for (int o = 16; o > 0; o >>= 1) {
        s  += __shfl_xor_sync(0xffffffffu, s,  o);
        sq += __shfl_xor_sync(0xffffffffu, sq, o);
    }
    __shared__ float sh1[8], sh2[8];
    int wid = t >> 5, lane = t & 31;
    if (lane == 0) { sh1[wid] = s; sh2[wid] = sq; }
    __syncthreads();
    float S = 0.f, SQ = 0.f;
    #pragma unroll
    for (int i = 0; i < 8; ++i) { S += sh1[i]; SQ += sh2[i]; }
    float mean = S * (1.f/256.f);
    float var  = SQ * (1.f/256.f) - mean * mean;
    y[(size_t)row * 256 + t] = (v - mean) * rsqrtf(var + 1e-5f) * g[t] + b[t];
}

// ---------------- attention-weight softmax over L*P=16 ----------------------
__global__ void awsm_kernel(const float* __restrict__ in, float* __restrict__ out) {
    int i = blockIdx.x * blockDim.x + threadIdx.x;
    if (i >= MQ * HHV) return;
    int bq = i >> 3, h = i & 7;
    const float* p = in + (size_t)bq * 128 + h * 16;
    float vals[16], mx = -1e30f;
    #pragma unroll
    for (int k = 0; k < 16; ++k) { vals[k] = p[k]; mx = fmaxf(mx, vals[k]); }
    float sum = 0.f;
    #pragma unroll
    for (int k = 0; k < 16; ++k) { vals[k] = __expf(vals[k] - mx); sum += vals[k]; }
    float inv = 1.f / sum;
    float* o = out + (size_t)bq * 128 + h * 16;
    #pragma unroll
    for (int k = 0; k < 16; ++k) o[k] = vals[k] * inv;
}

// ---------------- deformable sampling: warp per (b,q,h) ---------------------
__global__ __launch_bounds__(256) void deform_kernel(
    const float* __restrict__ val, const float* __restrict__ ref,
    const float* __restrict__ offs, const float* __restrict__ aw,
    float* __restrict__ out)
{
    const int gw = (blockIdx.x * blockDim.x + threadIdx.x) >> 5;
    const int lane = threadIdx.x & 31;
    if (gw >= MQ * HHV) return;
    const int bq = gw >> 3, h = gw & 7;
    const int b = bq >> 10;

    const int starts[4] = {0, 16384, 20480, 21504};
    const int WL[4]     = {128, 64, 32, 16};

    const float* offp = offs + (size_t)bq * 256 + h * 32;
    const float* awp  = aw   + (size_t)bq * 128 + h * 16;
    const float* refp = ref  + (size_t)bq * 8;

    float acc = 0.f;
    #pragma unroll
    for (int l = 0; l < 4; ++l) {
        const int wl = WL[l];
        const float fwl = (float)wl;
        const float rx = refp[l*2+0], ry = refp[l*2+1];
        const int base_l = b * LSRCV + starts[l];
        #pragma unroll
        for (int p = 0; p < 4; ++p) {
            float ox = offp[l*8 + p*2 + 0];
            float oy = offp[l*8 + p*2 + 1];
            float a  = awp[l*4 + p];
            float x = (rx + ox / fwl) * fwl - 0.5f;
            float y = (ry + oy / fwl) * fwl - 0.5f;
            float x0f = floorf(x), y0f = floorf(y);
            int x0 = (int)x0f, y0 = (int)y0f;
            float wx1 = x - x0f, wx0 = 1.f - wx1;
            float wy1 = y - y0f, wy0 = 1.f - wy1;
            #pragma unroll
            for (int dy = 0; dy < 2; ++dy) {
                #pragma unroll
                for (int dx = 0; dx < 2; ++dx) {
                    int xi = x0 + dx, yi = y0 + dy;
                    if (xi >= 0 && xi < wl && yi >= 0 && yi < wl) {
                        float wgt = (dx ? wx1 : wx0) * (dy ? wy1 : wy0);
                        float vv = val[((size_t)(base_l + yi*wl + xi))*CCV + h*32 + lane];
                        acc += a * wgt * vv;
                    }
                }
            }
        }
    }
    out[(size_t)bq * 256 + h * 32 + lane] = acc;
}

// ---------------- orchestration ---------------------------------------------
extern "C" void kernel_launch(void* const* d_in, const int* in_sizes, int n_in,
                              void* d_out, int out_size)
{
    const float* tgt   = (const float*)d_in[0];
    const float* qpos  = (const float*)d_in[1];
    const float* refp  = (const float*)d_in[2];
    const float* src   = (const float*)d_in[3];
    const float* in_w  = (const float*)d_in[4];
    const float* in_b  = (const float*)d_in[5];
    const float* sa_w  = (const float*)d_in[6];
    const float* sa_b  = (const float*)d_in[7];
    const float* off_w = (const float*)d_in[8];
    const float* off_b = (const float*)d_in[9];
    const float* aw_w  = (const float*)d_in[10];
    const float* aw_b  = (const float*)d_in[11];
    const float* val_w = (const float*)d_in[12];
    const float* val_b = (const float*)d_in[13];
    const float* co_w  = (const float*)d_in[14];
    const float* co_b  = (const float*)d_in[15];
    const float* ln1_g = (const float*)d_in[16];
    const float* ln1_b = (const float*)d_in[17];
    const float* ln2_g = (const float*)d_in[18];
    const float* ln2_b = (const float*)d_in[19];
    const float* ln3_g = (const float*)d_in[20];
    const float* ln3_b = (const float*)d_in[21];
    const float* f1_w  = (const float*)d_in[22];
    const float* f1_b  = (const float*)d_in[23];
    const float* f2_w  = (const float*)d_in[24];
    const float* f2_b  = (const float*)d_in[25];
    float* out = (float*)d_out;

    float *p_qk, *p_q, *p_k, *p_v, *p_attn, *p_res, *p_tgta, *p_value;
    float *p_q2, *p_off, *p_aw, *p_samp, *p_tgtb, *p_hid;
    cudaGetSymbolAddress((void**)&p_qk,   g_qk);
    cudaGetSymbolAddress((void**)&p_q,    g_q);
    cudaGetSymbolAddress((void**)&p_k,    g_k);
    cudaGetSymbolAddress((void**)&p_v,    g_v);
    cudaGetSymbolAddress((void**)&p_attn, g_attn);
    cudaGetSymbolAddress((void**)&p_res,  g_res);
    cudaGetSymbolAddress((void**)&p_tgta, g_tgta);
    cudaGetSymbolAddress((void**)&p_value,g_value);
    cudaGetSymbolAddress((void**)&p_q2,   g_q2);
    cudaGetSymbolAddress((void**)&p_off,  g_off);
    cudaGetSymbolAddress((void**)&p_aw,   g_aw);
    cudaGetSymbolAddress((void**)&p_samp, g_samp);
    cudaGetSymbolAddress((void**)&p_tgtb, g_tgtb);
    cudaGetSymbolAddress((void**)&p_hid,  g_hid);

    const int NQ = MQ * CCV;

    // ---- self-attention ----
    add_kernel<<<NQ/256, 256>>>(tgt, qpos, p_qk, NQ);
    gemm_tc<false,false><<<dim3(2,32), 256>>>(p_qk, in_w,           in_b,       nullptr, p_q, MQ, 256, 256);
    gemm_tc<false,false><<<dim3(2,32), 256>>>(p_qk, in_w + 256*256, in_b + 256, nullptr, p_k, MQ, 256, 256);
    gemm_tc<false,false><<<dim3(2,32), 256>>>(tgt,  in_w + 512*256, in_b + 512, nullptr, p_v, MQ, 256, 256);
    attn_kernel<<<dim3(32,128), 256>>>(p_q, p_k, p_v, p_attn);
    gemm_tc<false,true ><<<dim3(2,32), 256>>>(p_attn, sa_w, sa_b, tgt, p_res, MQ, 256, 256);
    ln_kernel<<<MQ, 256>>>(p_res, ln2_g, ln2_b, p_tgta);

    // ---- deformable cross-attention ----
    gemm_tc<false,false><<<dim3(2,680), 256>>>(src, val_w, val_b, nullptr, p_value, MS, 256, 256);
    add_kernel<<<NQ/256, 256>>>(p_tgta, qpos, p_q2, NQ);
    gemm_tc<false,false><<<dim3(2,32), 256>>>(p_q2, off_w, off_b, nullptr, p_off, MQ, 256, 256);
    gemm_tc<false,false><<<dim3(1,32), 256>>>(p_q2, aw_w,  aw_b,  nullptr, p_res, MQ, 128, 256);
    awsm_kernel<<<128, 256>>>(p_res, p_aw);
    deform_kernel<<<4096, 256>>>(p_value, refp, p_off, p_aw, p_samp);
    gemm_tc<false,true ><<<dim3(2,32), 256>>>(p_samp, co_w, co_b, p_tgta, p_res, MQ, 256, 256);
    ln_kernel<<<MQ, 256>>>(p_res, ln1_g, ln1_b, p_tgtb);

    // ---- FFN ----
    gemm_tc<true ,false><<<dim3(8,32), 256>>>(p_tgtb, f1_w, f1_b, nullptr, p_hid, MQ, 1024, 256);
    gemm_tc<false,true ><<<dim3(2,32), 256>>>(p_hid, f2_w, f2_b, p_tgtb, p_res, MQ, 256, 1024);
    ln_kernel<<<MQ, 256>>>(p_res, ln3_g, ln3_b, out);
}

// round 7
// speedup vs baseline: 1.7310x; 1.7310x over previous
#include <cuda_runtime.h>
#include <cuda_bf16.h>
#include <math.h>
#include <stdint.h>

#define BB   4
#define LQV  1024
#define CCV  256
#define HHV  8
#define DHV  32
#define DFFV 1024
#define LSRCV 21760
#define MQ (BB*LQV)     // 4096
#define MS (BB*LSRCV)   // 87040

// ---------------- fp32 scratch ----------------------------------------------
__device__ float g_q   [MQ*CCV];
__device__ float g_k   [MQ*CCV];
__device__ float g_v   [MQ*CCV];
__device__ float g_res [MQ*CCV];
__device__ float g_tgta[MQ*CCV];
__device__ float g_value[(size_t)MS*CCV];
__device__ float g_off [MQ*CCV];
__device__ float g_aw  [MQ*128];
__device__ float g_tgtb[MQ*CCV];

// ---------------- bf16 scratch ----------------------------------------------
__device__ __nv_bfloat16 b_qk  [MQ*CCV];
__device__ __nv_bfloat16 b_tgt [MQ*CCV];
__device__ __nv_bfloat16 b_attn[MQ*CCV];
__device__ __nv_bfloat16 b_src [(size_t)MS*CCV];
__device__ __nv_bfloat16 b_q2  [MQ*CCV];
__device__ __nv_bfloat16 b_samp[MQ*CCV];
__device__ __nv_bfloat16 b_tgtb[MQ*CCV];
__device__ __nv_bfloat16 b_hid [MQ*DFFV];
__device__ __nv_bfloat16 b_inw [3*CCV*CCV];
__device__ __nv_bfloat16 b_saw [CCV*CCV];
__device__ __nv_bfloat16 b_valw[CCV*CCV];
__device__ __nv_bfloat16 b_offw[CCV*CCV];
__device__ __nv_bfloat16 b_aww [128*CCV];
__device__ __nv_bfloat16 b_cow [CCV*CCV];
__device__ __nv_bfloat16 b_f1w [DFFV*CCV];
__device__ __nv_bfloat16 b_f2w [CCV*DFFV];

__device__ __forceinline__ uint32_t smem_u32(const void* p) {
    uint32_t a;
    asm("{ .reg .u64 t; cvta.to.shared.u64 t, %1; cvt.u32.u64 %0, t; }"
        : "=r"(a) : "l"(p));
    return a;
}

// ---------------- fp32 -> bf16 convert (vectorized) --------------------------
__global__ void cvt_kernel(const float* __restrict__ in,
                           __nv_bfloat16* __restrict__ out, int n4) {
    int i = blockIdx.x * blockDim.x + threadIdx.x;
    if (i >= n4) return;
    float4 v = ((const float4*)in)[i];
    __nv_bfloat162 lo = __floats2bfloat162_rn(v.x, v.y);
    __nv_bfloat162 hi = __floats2bfloat162_rn(v.z, v.w);
    ((uint2*)out)[i] = make_uint2(*(uint32_t*)&lo, *(uint32_t*)&hi);
}

// ---------------- add -> bf16 -----------------------------------------------
__global__ void add_bf_kernel(const float* __restrict__ a, const float* __restrict__ b,
                              __nv_bfloat16* __restrict__ o, int n2) {
    int i = blockIdx.x * blockDim.x + threadIdx.x;
    if (i >= n2) return;
    float2 va = ((const float2*)a)[i];
    float2 vb = ((const float2*)b)[i];
    __nv_bfloat162 r = __floats2bfloat162_rn(va.x + vb.x, va.y + vb.y);
    ((uint32_t*)o)[i] = *(uint32_t*)&r;
}

// ---------------- bf16 mma.sync GEMM with cp.async + ldmatrix ----------------
// C = A(MxK)bf16 * W(NxK)bf16^T + bias [+resid][relu]; out fp32 or bf16.
// Tile 128x128x32, 2-stage cp.async pipeline, 8 warps of 64x32.
#define RSTRIDE 80   // smem row stride bytes (32 bf16 = 64B data + 16B pad)

template<bool RELU, bool RESID, bool OUTBF>
__global__ __launch_bounds__(256, 2) void gemmb(
    const __nv_bfloat16* __restrict__ A, const __nv_bfloat16* __restrict__ W,
    const float* __restrict__ bias, const float* __restrict__ resid,
    float* __restrict__ Cf, __nv_bfloat16* __restrict__ Cb, int M, int N, int K)
{
    __shared__ __align__(16) char sm[2][2 * 128 * RSTRIDE];  // [stage][A|B]

    const int tid  = threadIdx.x;
    const int wid  = tid >> 5;
    const int lane = tid & 31;
    const int bm = blockIdx.y * 128;
    const int bn = blockIdx.x * 128;
    const int wm = (wid & 1) * 64;
    const int wn = (wid >> 1) * 32;

    float acc[4][4][4] = {};

    const int NS = K >> 5;

    // per-thread load chunks: 512 16B chunks per matrix per stage, 2 per thread
    const int c0r = tid >> 2,        c0c = tid & 3;
    const int c1r = (tid + 256) >> 2, c1c = (tid + 256) & 3;

    auto stage_load = [&](int s, int slab) {
        const int kt = slab * 32;
        char* sA = sm[s];
        char* sB = sm[s] + 128 * RSTRIDE;
        {
            const void* gA = A + (size_t)(bm + c0r) * K + kt + c0c * 8;
            const void* gB = W + (size_t)(bn + c0r) * K + kt + c0c * 8;
            uint32_t dA = smem_u32(sA + c0r * RSTRIDE + c0c * 16);
            uint32_t dB = smem_u32(sB + c0r * RSTRIDE + c0c * 16);
            asm volatile("cp.async.cg.shared.global [%0], [%1], 16;" :: "r"(dA), "l"(gA));
            asm volatile("cp.async.cg.shared.global [%0], [%1], 16;" :: "r"(dB), "l"(gB));
        }
        {
            const void* gA = A + (size_t)(bm + c1r) * K + kt + c1c * 8;
            const void* gB = W + (size_t)(bn + c1r) * K + kt + c1c * 8;
            uint32_t dA = smem_u32(sA + c1r * RSTRIDE + c1c * 16);
            uint32_t dB = smem_u32(sB + c1r * RSTRIDE + c1c * 16);
            asm volatile("cp.async.cg.shared.global [%0], [%1], 16;" :: "r"(dA), "l"(gA));
            asm volatile("cp.async.cg.shared.global [%0], [%1], 16;" :: "r"(dB), "l"(gB));
        }
        asm volatile("cp.async.commit_group;");
    };

    stage_load(0, 0);
    stage_load(1, 1);

    for (int s = 0; s < NS; ++s) {
        if (s + 1 < NS) asm volatile("cp.async.wait_group 1;");
        else            asm volatile("cp.async.wait_group 0;");
        __syncthreads();

        char* sA = sm[s & 1];
        char* sB = sm[s & 1] + 128 * RSTRIDE;

        #pragma unroll
        for (int h = 0; h < 2; ++h) {
            const int kb = h * 32 + (lane >> 4) * 16;   // byte offset along k
            uint32_t a[4][4], b[4][2];
            #pragma unroll
            for (int i = 0; i < 4; ++i) {
                uint32_t addr = smem_u32(sA + (wm + i*16 + (lane & 15)) * RSTRIDE + kb);
                asm volatile("ldmatrix.sync.aligned.m8n8.x4.shared.b16 {%0,%1,%2,%3}, [%4];"
                    : "=r"(a[i][0]), "=r"(a[i][1]), "=r"(a[i][2]), "=r"(a[i][3]) : "r"(addr));
            }
            #pragma unroll
            for (int jj = 0; jj < 2; ++jj) {
                uint32_t r0, r1, r2, r3;
                uint32_t addr = smem_u32(sB + (wn + jj*16 + (lane & 15)) * RSTRIDE + kb);
                asm volatile("ldmatrix.sync.aligned.m8n8.x4.shared.b16 {%0,%1,%2,%3}, [%4];"
                    : "=r"(r0), "=r"(r1), "=r"(r2), "=r"(r3) : "r"(addr));
                b[jj*2  ][0] = r0; b[jj*2  ][1] = r2;
                b[jj*2+1][0] = r1; b[jj*2+1][1] = r3;
            }
            #pragma unroll
            for (int i = 0; i < 4; ++i)
                #pragma unroll
                for (int j = 0; j < 4; ++j)
                    asm volatile(
                        "mma.sync.aligned.m16n8k16.row.col.f32.bf16.bf16.f32 "
                        "{%0,%1,%2,%3},{%4,%5,%6,%7},{%8,%9},{%0,%1,%2,%3};"
                        : "+f"(acc[i][j][0]), "+f"(acc[i][j][1]),
                          "+f"(acc[i][j][2]), "+f"(acc[i][j][3])
                        : "r"(a[i][0]), "r"(a[i][1]), "r"(a[i][2]), "r"(a[i][3]),
                          "r"(b[j][0]), "r"(b[j][1]));
        }
        __syncthreads();
        if (s + 2 < NS) stage_load(s & 1, s + 2);
    }

    // epilogue: c0,c1 = (row, col2..col2+1); c2,c3 = (row+8, ...)
    #pragma unroll
    for (int i = 0; i < 4; ++i) {
        const int rbase = bm + wm + i*16 + (lane >> 2);
        #pragma unroll
        for (int rr = 0; rr < 2; ++rr) {
            const int r = rbase + rr * 8;
            #pragma unroll
            for (int j = 0; j < 4; ++j) {
                const int cc = bn + wn + j*8 + (lane & 3) * 2;
                float v0 = acc[i][j][rr*2+0] + bias[cc];
                float v1 = acc[i][j][rr*2+1] + bias[cc+1];
                if (RESID) {
                    float2 rv = *(const float2*)&resid[(size_t)r * N + cc];
                    v0 += rv.x; v1 += rv.y;
                }
                if (RELU) { v0 = fmaxf(v0, 0.f); v1 = fmaxf(v1, 0.f); }
                if (OUTBF) {
                    __nv_bfloat162 bv = __floats2bfloat162_rn(v0, v1);
                    *(uint32_t*)&Cb[(size_t)r * N + cc] = *(uint32_t*)&bv;
                } else {
                    *(float2*)&Cf[(size_t)r * N + cc] = make_float2(v0, v1);
                }
            }
        }
    }
}

// ---------------- flash attention: warp-per-query, DH=32 (bf16 out) ---------
__global__ __launch_bounds__(256) void attn_kernel(
    const float* __restrict__ Q, const float* __restrict__ Kb,
    const float* __restrict__ Vb, __nv_bfloat16* __restrict__ O)
{
    __shared__ float Ks[64][33];
    __shared__ float Vs[64][33];
    __shared__ float Ps[8][64];
    const int bh = blockIdx.x;
    const int b = bh >> 3, h = bh & 7;
    const int w = threadIdx.x >> 5;
    const int lane = threadIdx.x & 31;
    const int q = blockIdx.y * 8 + w;

    const float scale = 0.17677669529663687f;
    float qv = Q[((size_t)(b*LQV + q))*CCV + h*DHV + lane] * scale;
    float qr[32];
    #pragma unroll
    for (int d = 0; d < 32; ++d) qr[d] = __shfl_sync(0xffffffffu, qv, d);

    float m = -1e30f, l = 0.f, acc = 0.f;

    for (int kt = 0; kt < LQV; kt += 64) {
        for (int i = threadIdx.x; i < 64*32; i += 256) {
            int r = i >> 5, c = i & 31;
            size_t gi = ((size_t)(b*LQV + kt + r))*CCV + h*DHV + c;
            Ks[r][c] = Kb[gi];
            Vs[r][c] = Vb[gi];
        }
        __syncthreads();

        float s0 = 0.f, s1 = 0.f;
        #pragma unroll
        for (int d = 0; d < 32; ++d) {
            s0 += qr[d] * Ks[lane][d];
            s1 += qr[d] * Ks[lane+32][d];
        }
        float tmax = fmaxf(s0, s1);
        #pragma unroll
        for (int o = 16; o > 0; o >>= 1)
            tmax = fmaxf(tmax, __shfl_xor_sync(0xffffffffu, tmax, o));
        float mn = fmaxf(m, tmax);
        float p0 = __expf(s0 - mn), p1 = __expf(s1 - mn);
        float sc = __expf(m - mn);
        float ps = p0 + p1;
        #pragma unroll
        for (int o = 16; o > 0; o >>= 1)
            ps += __shfl_xor_sync(0xffffffffu, ps, o);
        l = l * sc + ps;
        m = mn;
        Ps[w][lane] = p0; Ps[w][lane+32] = p1;
        __syncwarp();
        float a = 0.f;
        #pragma unroll
        for (int j = 0; j < 64; ++j) a += Ps[w][j] * Vs[j][lane];
        acc = acc * sc + a;
        __syncthreads();
    }
    O[((size_t)(b*LQV + q))*CCV + h*DHV + lane] = __float2bfloat16(acc / l);
}

// ---------------- LayerNorm (optionally also emit bf16) ---------------------
template<bool BF>
__global__ __launch_bounds__(256) void ln_kernel(
    const float* __restrict__ x, const float* __restrict__ g,
    const float* __restrict__ b, float* __restrict__ y,
    __nv_bfloat16* __restrict__ ybf)
{
    const int row = blockIdx.x;
    const int t = threadIdx.x;
    float v = x[(size_t)row * 256 + t];
    float s = v, sq = v * v;
    #pragma unroll
    for (int o = 16; o > 0; o >>= 1) {
        s  += __shfl_xor_sync(0xffffffffu, s,  o);
        sq += __shfl_xor_sync(0xffffffffu, sq, o);
    }
    __shared__ float sh1[8], sh2[8];
    int wid = t >> 5, lane = t & 31;
    if (lane == 0) { sh1[wid] = s; sh2[wid] = sq; }
    __syncthreads();
    float S = 0.f, SQ = 0.f;
    #pragma unroll
    for (int i = 0; i < 8; ++i) { S += sh1[i]; SQ += sh2[i]; }
    float mean = S * (1.f/256.f);
    float var  = SQ * (1.f/256.f) - mean * mean;
    float r = (v - mean) * rsqrtf(var + 1e-5f) * g[t] + b[t];
    y[(size_t)row * 256 + t] = r;
    if (BF) ybf[(size_t)row * 256 + t] = __float2bfloat16(r);
}

// ---------------- attention-weight softmax over L*P=16 ----------------------
__global__ void awsm_kernel(const float* __restrict__ in, float* __restrict__ out) {
    int i = blockIdx.x * blockDim.x + threadIdx.x;
    if (i >= MQ * HHV) return;
    int bq = i >> 3, h = i & 7;
    const float* p = in + (size_t)bq * 128 + h * 16;
    float vals[16], mx = -1e30f;
    #pragma unroll
    for (int k = 0; k < 16; ++k) { vals[k] = p[k]; mx = fmaxf(mx, vals[k]); }
    float sum = 0.f;
    #pragma unroll
    for (int k = 0; k < 16; ++k) { vals[k] = __expf(vals[k] - mx); sum += vals[k]; }
    float inv = 1.f / sum;
    float* o = out + (size_t)bq * 128 + h * 16;
    #pragma unroll
    for (int k = 0; k < 16; ++k) o[k] = vals[k] * inv;
}

// ---------------- deformable sampling: warp per (b,q,h), bf16 out -----------
__global__ __launch_bounds__(256) void deform_kernel(
    const float* __restrict__ val, const float* __restrict__ ref,
    const float* __restrict__ offs, const float* __restrict__ aw,
    __nv_bfloat16* __restrict__ out)
{
    const int gw = (blockIdx.x * blockDim.x + threadIdx.x) >> 5;
    const int lane = threadIdx.x & 31;
    if (gw >= MQ * HHV) return;
    const int bq = gw >> 3, h = gw & 7;
    const int b = bq >> 10;

    const int starts[4] = {0, 16384, 20480, 21504};
    const int WL[4]     = {128, 64, 32, 16};

    const float* offp = offs + (size_t)bq * 256 + h * 32;
    const float* awp  = aw   + (size_t)bq * 128 + h * 16;
    const float* refp = ref  + (size_t)bq * 8;

    float acc = 0.f;
    #pragma unroll
    for (int l = 0; l < 4; ++l) {
        const int wl = WL[l];
        const float fwl = (float)wl;
        const float rx = refp[l*2+0], ry = refp[l*2+1];
        const int base_l = b * LSRCV + starts[l];
        #pragma unroll
        for (int p = 0; p < 4; ++p) {
            float ox = offp[l*8 + p*2 + 0];
            float oy = offp[l*8 + p*2 + 1];
            float a  = awp[l*4 + p];
            float x = (rx + ox / fwl) * fwl - 0.5f;
            float y = (ry + oy / fwl) * fwl - 0.5f;
            float x0f = floorf(x), y0f = floorf(y);
            int x0 = (int)x0f, y0 = (int)y0f;
            float wx1 = x - x0f, wx0 = 1.f - wx1;
            float wy1 = y - y0f, wy0 = 1.f - wy1;
            #pragma unroll
            for (int dy = 0; dy < 2; ++dy) {
                #pragma unroll
                for (int dx = 0; dx < 2; ++dx) {
                    int xi = x0 + dx, yi = y0 + dy;
                    if (xi >= 0 && xi < wl && yi >= 0 && yi < wl) {
                        float wgt = (dx ? wx1 : wx0) * (dy ? wy1 : wy0);
                        float vv = val[((size_t)(base_l + yi*wl + xi))*CCV + h*32 + lane];
                        acc += a * wgt * vv;
                    }
                }
            }
        }
    }
    out[(size_t)bq * 256 + h * 32 + lane] = __float2bfloat16(acc);
}

// ---------------- orchestration ---------------------------------------------
extern "C" void kernel_launch(void* const* d_in, const int* in_sizes, int n_in,
                              void* d_out, int out_size)
{
    const float* tgt   = (const float*)d_in[0];
    const float* qpos  = (const float*)d_in[1];
    const float* refp  = (const float*)d_in[2];
    const float* src   = (const float*)d_in[3];
    const float* in_w  = (const float*)d_in[4];
    const float* in_b  = (const float*)d_in[5];
    const float* sa_w  = (const float*)d_in[6];
    const float* sa_b  = (const float*)d_in[7];
    const float* off_w = (const float*)d_in[8];
    const float* off_b = (const float*)d_in[9];
    const float* aw_w  = (const float*)d_in[10];
    const float* aw_b  = (const float*)d_in[11];
    const float* val_w = (const float*)d_in[12];
    const float* val_b = (const float*)d_in[13];
    const float* co_w  = (const float*)d_in[14];
    const float* co_b  = (const float*)d_in[15];
    const float* ln1_g = (const float*)d_in[16];
    const float* ln1_b = (const float*)d_in[17];
    const float* ln2_g = (const float*)d_in[18];
    const float* ln2_b = (const float*)d_in[19];
    const float* ln3_g = (const float*)d_in[20];
    const float* ln3_b = (const float*)d_in[21];
    const float* f1_w  = (const float*)d_in[22];
    const float* f1_b  = (const float*)d_in[23];
    const float* f2_w  = (const float*)d_in[24];
    const float* f2_b  = (const float*)d_in[25];
    float* out = (float*)d_out;

    float *p_q, *p_k, *p_v, *p_res, *p_tgta, *p_value, *p_off, *p_aw, *p_tgtb;
    cudaGetSymbolAddress((void**)&p_q,    g_q);
    cudaGetSymbolAddress((void**)&p_k,    g_k);
    cudaGetSymbolAddress((void**)&p_v,    g_v);
    cudaGetSymbolAddress((void**)&p_res,  g_res);
    cudaGetSymbolAddress((void**)&p_tgta, g_tgta);
    cudaGetSymbolAddress((void**)&p_value,g_value);
    cudaGetSymbolAddress((void**)&p_off,  g_off);
    cudaGetSymbolAddress((void**)&p_aw,   g_aw);
    cudaGetSymbolAddress((void**)&p_tgtb, g_tgtb);

    __nv_bfloat16 *q_qk, *q_tgt, *q_attn, *q_src, *q_q2, *q_samp, *q_tgtb, *q_hid;
    __nv_bfloat16 *w_in, *w_sa, *w_val, *w_off, *w_aw, *w_co, *w_f1, *w_f2;
    cudaGetSymbolAddress((void**)&q_qk,   b_qk);
    cudaGetSymbolAddress((void**)&q_tgt,  b_tgt);
    cudaGetSymbolAddress((void**)&q_attn, b_attn);
    cudaGetSymbolAddress((void**)&q_src,  b_src);
    cudaGetSymbolAddress((void**)&q_q2,   b_q2);
    cudaGetSymbolAddress((void**)&q_samp, b_samp);
    cudaGetSymbolAddress((void**)&q_tgtb, b_tgtb);
    cudaGetSymbolAddress((void**)&q_hid,  b_hid);
    cudaGetSymbolAddress((void**)&w_in,   b_inw);
    cudaGetSymbolAddress((void**)&w_sa,   b_saw);
    cudaGetSymbolAddress((void**)&w_val,  b_valw);
    cudaGetSymbolAddress((void**)&w_off,  b_offw);
    cudaGetSymbolAddress((void**)&w_aw,   b_aww);
    cudaGetSymbolAddress((void**)&w_co,   b_cow);
    cudaGetSymbolAddress((void**)&w_f1,   b_f1w);
    cudaGetSymbolAddress((void**)&w_f2,   b_f2w);

    const int NQ = MQ * CCV;   // 1048576

    #define CVT(src_, dst_, n_) cvt_kernel<<<((n_)/4 + 255)/256, 256>>>(src_, dst_, (n_)/4)
    CVT(tgt,   q_tgt, NQ);
    CVT(src,   q_src, MS*CCV);
    CVT(in_w,  w_in,  3*CCV*CCV);
    CVT(sa_w,  w_sa,  CCV*CCV);
    CVT(val_w, w_val, CCV*CCV);
    CVT(off_w, w_off, CCV*CCV);
    CVT(aw_w,  w_aw,  128*CCV);
    CVT(co_w,  w_co,  CCV*CCV);
    CVT(f1_w,  w_f1,  DFFV*CCV);
    CVT(f2_w,  w_f2,  CCV*DFFV);

    // ---- self-attention ----
    add_bf_kernel<<<NQ/512, 256>>>(tgt, qpos, q_qk, NQ/2);
    gemmb<false,false,false><<<dim3(2,32), 256>>>(q_qk, w_in,               in_b,       nullptr, p_q, nullptr, MQ, 256, 256);
    gemmb<false,false,false><<<dim3(2,32), 256>>>(q_qk, w_in + 256*256,     in_b + 256, nullptr, p_k, nullptr, MQ, 256, 256);
    gemmb<false,false,false><<<dim3(2,32), 256>>>(q_tgt, w_in + 512*256,    in_b + 512, nullptr, p_v, nullptr, MQ, 256, 256);
    attn_kernel<<<dim3(32,128), 256>>>(p_q, p_k, p_v, q_attn);
    gemmb<false,true ,false><<<dim3(2,32), 256>>>(q_attn, w_sa, sa_b, tgt, p_res, nullptr, MQ, 256, 256);
    ln_kernel<false><<<MQ, 256>>>(p_res, ln2_g, ln2_b, p_tgta, nullptr);

    // ---- deformable cross-attention ----
    gemmb<false,false,false><<<dim3(2,680), 256>>>(q_src, w_val, val_b, nullptr, p_value, nullptr, MS, 256, 256);
    add_bf_kernel<<<NQ/512, 256>>>(p_tgta, qpos, q_q2, NQ/2);
    gemmb<false,false,false><<<dim3(2,32), 256>>>(q_q2, w_off, off_b, nullptr, p_off, nullptr, MQ, 256, 256);
    gemmb<false,false,false><<<dim3(1,32), 256>>>(q_q2, w_aw,  aw_b,  nullptr, p_res, nullptr, MQ, 128, 256);
    awsm_kernel<<<128, 256>>>(p_res, p_aw);
    deform_kernel<<<4096, 256>>>(p_value, refp, p_off, p_aw, q_samp);
    gemmb<false,true ,false><<<dim3(2,32), 256>>>(q_samp, w_co, co_b, p_tgta, p_res, nullptr, MQ, 256, 256);
    ln_kernel<true ><<<MQ, 256>>>(p_res, ln1_g, ln1_b, p_tgtb, q_tgtb);

    // ---- FFN ----
    gemmb<true ,false,true ><<<dim3(8,32), 256>>>(q_tgtb, w_f1, f1_b, nullptr, nullptr, q_hid, MQ, 1024, 256);
    gemmb<false,true ,false><<<dim3(2,32), 256>>>(q_hid, w_f2, f2_b, p_tgtb, p_res, nullptr, MQ, 256, 1024);
    ln_kernel<false><<<MQ, 256>>>(p_res, ln3_g, ln3_b, out, nullptr);
}

// round 9
// speedup vs baseline: 1.8650x; 1.0775x over previous
#include <cuda_runtime.h>
#include <cuda_bf16.h>
#include <math.h>
#include <stdint.h>

#define BB   4
#define LQV  1024
#define CCV  256
#define HHV  8
#define DHV  32
#define DFFV 1024
#define LSRCV 21760
#define MQ (BB*LQV)     // 4096
#define MS (BB*LSRCV)   // 87040

// ---------------- fp32 scratch ----------------------------------------------
__device__ float g_qkq [MQ*512];
__device__ float g_v   [MQ*CCV];
__device__ float g_res [MQ*CCV];
__device__ float g_tgta[MQ*CCV];
__device__ float g_value[(size_t)MS*CCV];
__device__ float g_off [MQ*CCV];
__device__ float g_aw  [MQ*128];
__device__ float g_tgtb[MQ*CCV];

// ---------------- bf16 scratch ----------------------------------------------
__device__ __nv_bfloat16 b_qk  [MQ*CCV];
__device__ __nv_bfloat16 b_tgt [MQ*CCV];
__device__ __nv_bfloat16 b_attn[MQ*CCV];
__device__ __nv_bfloat16 b_src [(size_t)MS*CCV];
__device__ __nv_bfloat16 b_q2  [MQ*CCV];
__device__ __nv_bfloat16 b_samp[MQ*CCV];
__device__ __nv_bfloat16 b_tgtb[MQ*CCV];
__device__ __nv_bfloat16 b_hid [MQ*DFFV];
__device__ __nv_bfloat16 b_inw [3*CCV*CCV];
__device__ __nv_bfloat16 b_saw [CCV*CCV];
__device__ __nv_bfloat16 b_valw[CCV*CCV];
__device__ __nv_bfloat16 b_offw[CCV*CCV];
__device__ __nv_bfloat16 b_aww [128*CCV];
__device__ __nv_bfloat16 b_cow [CCV*CCV];
__device__ __nv_bfloat16 b_f1w [DFFV*CCV];
__device__ __nv_bfloat16 b_f2w [CCV*DFFV];

__device__ __forceinline__ uint32_t smem_u32(const void* p) {
    uint32_t a;
    asm("{ .reg .u64 t; cvta.to.shared.u64 t, %1; cvt.u32.u64 %0, t; }"
        : "=r"(a) : "l"(p));
    return a;
}

// ---------------- fused fp32 -> bf16 convert (10 segments) -------------------
struct CvtArgs {
    const float* s[10];
    __nv_bfloat16* d[10];
    int end4[10];
};

__global__ void cvt_all(CvtArgs a, int total4) {
    int i = blockIdx.x * blockDim.x + threadIdx.x;
    if (i >= total4) return;
    int seg = 0;
    #pragma unroll
    for (int k = 0; k < 9; ++k) if (i >= a.end4[k]) seg = k + 1;
    int base = seg ? a.end4[seg - 1] : 0;
    int li = i - base;
    float4 v = ((const float4*)a.s[seg])[li];
    __nv_bfloat162 lo = __floats2bfloat162_rn(v.x, v.y);
    __nv_bfloat162 hi = __floats2bfloat162_rn(v.z, v.w);
    ((uint2*)a.d[seg])[li] = make_uint2(*(uint32_t*)&lo, *(uint32_t*)&hi);
}

// ---------------- add -> bf16 -----------------------------------------------
__global__ void add_bf_kernel(const float* __restrict__ a, const float* __restrict__ b,
                              __nv_bfloat16* __restrict__ o, int n2) {
    int i = blockIdx.x * blockDim.x + threadIdx.x;
    if (i >= n2) return;
    float2 va = ((const float2*)a)[i];
    float2 vb = ((const float2*)b)[i];
    __nv_bfloat162 r = __floats2bfloat162_rn(va.x + vb.x, va.y + vb.y);
    ((uint32_t*)o)[i] = *(uint32_t*)&r;
}

// ---------------- bf16 mma.sync GEMM, templated BM ---------------------------
// C = A(MxK)bf16 * W(NxK)bf16^T + bias [+resid][relu]; out fp32 or bf16.
// Tile BMx128x32, 2-stage cp.async pipeline, 8 warps.
#define RSTRIDE 80

template<int BM, bool RELU, bool RESID, bool OUTBF>
__global__ __launch_bounds__(256, (BM == 64) ? 3 : 2) void gemmb(
    const __nv_bfloat16* __restrict__ A, const __nv_bfloat16* __restrict__ W,
    const float* __restrict__ bias, const float* __restrict__ resid,
    float* __restrict__ Cf, __nv_bfloat16* __restrict__ Cb, int M, int N, int K)
{
    constexpr int MI = BM / 32;          // mma i-tiles per warp
    constexpr int CH = (BM + 128) / 64;  // 16B chunks per thread per stage
    __shared__ __align__(16) char sm[2][(BM + 128) * RSTRIDE];

    const int tid  = threadIdx.x;
    const int wid  = tid >> 5;
    const int lane = tid & 31;
    const int bm = blockIdx.y * BM;
    const int bn = blockIdx.x * 128;
    const int wm = (wid & 1) * (BM / 2);
    const int wn = (wid >> 1) * 32;

    float acc[MI][4][4] = {};
    const int NS = K >> 5;

    auto stage_load = [&](int s, int slab) {
        const int kt = slab * 32;
        char* base = sm[s];
        #pragma unroll
        for (int u = 0; u < CH; ++u) {
            int idx = tid + u * 256;
            bool isB = idx >= BM * 4;
            int row = isB ? ((idx - BM * 4) >> 2) : (idx >> 2);
            int col = idx & 3;
            const void* g = isB ? (const void*)(W + (size_t)(bn + row) * K + kt + col * 8)
                                : (const void*)(A + (size_t)(bm + row) * K + kt + col * 8);
            uint32_t d = smem_u32(base + (isB ? BM * RSTRIDE : 0) + row * RSTRIDE + col * 16);
            asm volatile("cp.async.cg.shared.global [%0], [%1], 16;" :: "r"(d), "l"(g));
        }
        asm volatile("cp.async.commit_group;");
    };

    stage_load(0, 0);
    stage_load(1, 1);

    for (int s = 0; s < NS; ++s) {
        if (s + 1 < NS) asm volatile("cp.async.wait_group 1;");
        else            asm volatile("cp.async.wait_group 0;");
        __syncthreads();

        char* sA = sm[s & 1];
        char* sB = sm[s & 1] + BM * RSTRIDE;

        #pragma unroll
        for (int h = 0; h < 2; ++h) {
            const int kb = h * 32 + (lane >> 4) * 16;
            uint32_t a[MI][4], b[4][2];
            #pragma unroll
            for (int i = 0; i < MI; ++i) {
                uint32_t addr = smem_u32(sA + (wm + i*16 + (lane & 15)) * RSTRIDE + kb);
                asm volatile("ldmatrix.sync.aligned.m8n8.x4.shared.b16 {%0,%1,%2,%3}, [%4];"
                    : "=r"(a[i][0]), "=r"(a[i][1]), "=r"(a[i][2]), "=r"(a[i][3]) : "r"(addr));
            }
            #pragma unroll
            for (int jj = 0; jj < 2; ++jj) {
                uint32_t r0, r1, r2, r3;
                uint32_t addr = smem_u32(sB + (wn + jj*16 + (lane & 15)) * RSTRIDE + kb);
                asm volatile("ldmatrix.sync.aligned.m8n8.x4.shared.b16 {%0,%1,%2,%3}, [%4];"
                    : "=r"(r0), "=r"(r1), "=r"(r2), "=r"(r3) : "r"(addr));
                b[jj*2  ][0] = r0; b[jj*2  ][1] = r2;
                b[jj*2+1][0] = r1; b[jj*2+1][1] = r3;
            }
            #pragma unroll
            for (int i = 0; i < MI; ++i)
                #pragma unroll
                for (int j = 0; j < 4; ++j)
                    asm volatile(
                        "mma.sync.aligned.m16n8k16.row.col.f32.bf16.bf16.f32 "
                        "{%0,%1,%2,%3},{%4,%5,%6,%7},{%8,%9},{%0,%1,%2,%3};"
                        : "+f"(acc[i][j][0]), "+f"(acc[i][j][1]),
                          "+f"(acc[i][j][2]), "+f"(acc[i][j][3])
                        : "r"(a[i][0]), "r"(a[i][1]), "r"(a[i][2]), "r"(a[i][3]),
                          "r"(b[j][0]), "r"(b[j][1]));
        }
        __syncthreads();
        if (s + 2 < NS) stage_load(s & 1, s + 2);
    }

    #pragma unroll
    for (int i = 0; i < MI; ++i) {
        const int rbase = bm + wm + i*16 + (lane >> 2);
        #pragma unroll
        for (int rr = 0; rr < 2; ++rr) {
            const int r = rbase + rr * 8;
            #pragma unroll
            for (int j = 0; j < 4; ++j) {
                const int cc = bn + wn + j*8 + (lane & 3) * 2;
                float v0 = acc[i][j][rr*2+0] + bias[cc];
                float v1 = acc[i][j][rr*2+1] + bias[cc+1];
                if (RESID) {
                    float2 rv = *(const float2*)&resid[(size_t)r * N + cc];
                    v0 += rv.x; v1 += rv.y;
                }
                if (RELU) { v0 = fmaxf(v0, 0.f); v1 = fmaxf(v1, 0.f); }
                if (OUTBF) {
                    __nv_bfloat162 bv = __floats2bfloat162_rn(v0, v1);
                    *(uint32_t*)&Cb[(size_t)r * N + cc] = *(uint32_t*)&bv;
                } else {
                    *(float2*)&Cf[(size_t)r * N + cc] = make_float2(v0, v1);
                }
            }
        }
    }
}

// ---------------- flash attention: f32x2 packed, Q/K stride 512 --------------
__global__ __launch_bounds__(256) void attn_kernel(
    const float* __restrict__ Q, const float* __restrict__ Kb,
    const float* __restrict__ Vb, __nv_bfloat16* __restrict__ O)
{
    __shared__ __align__(16) float Kst[32][66];  // [chan][permuted row]
    __shared__ __align__(16) float Vt [32][66];  // [chan][row]
    __shared__ __align__(16) float Ps [8][64];
    const int bh = blockIdx.x;
    const int b = bh >> 3, h = bh & 7;
    const int w = threadIdx.x >> 5;
    const int lane = threadIdx.x & 31;
    const int q = blockIdx.y * 8 + w;

    const float scale = 0.17677669529663687f;
    float qv = Q[((size_t)(b*LQV + q))*512 + h*DHV + lane] * scale;
    float qr[32];
    #pragma unroll
    for (int d = 0; d < 32; ++d) qr[d] = __shfl_sync(0xffffffffu, qv, d);

    float m = -1e30f, l = 0.f;
    uint64_t acc2 = 0;   // packed (acc_even_sum, acc_odd_sum)

    for (int kt = 0; kt < LQV; kt += 64) {
        for (int i = threadIdx.x; i < 64*32; i += 256) {
            int r = i >> 5, c = i & 31;
            Kst[c][2*(r & 31) + (r >> 5)] =
                Kb[((size_t)(b*LQV + kt + r))*512 + h*DHV + c];
            Vt[c][r] = Vb[((size_t)(b*LQV + kt + r))*CCV + h*DHV + c];
        }
        __syncthreads();

        // scores for rows (lane, lane+32) packed
        uint64_t s01 = 0;
        #pragma unroll
        for (int d = 0; d < 32; ++d) {
            uint64_t kvb = *(const uint64_t*)&Kst[d][2*lane];
            uint64_t av;
            asm("mov.b64 %0, {%1, %1};" : "=l"(av) : "f"(qr[d]));
            asm("fma.rn.f32x2 %0, %1, %2, %0;" : "+l"(s01) : "l"(av), "l"(kvb));
        }
        float s0, s1;
        asm("mov.b64 {%0, %1}, %2;" : "=f"(s0), "=f"(s1) : "l"(s01));

        float tmax = fmaxf(s0, s1);
        #pragma unroll
        for (int o = 16; o > 0; o >>= 1)
            tmax = fmaxf(tmax, __shfl_xor_sync(0xffffffffu, tmax, o));
        float mn = fmaxf(m, tmax);
        float p0 = __expf(s0 - mn), p1 = __expf(s1 - mn);
        float sc = __expf(m - mn);
        float ps = p0 + p1;
        #pragma unroll
        for (int o = 16; o > 0; o >>= 1)
            ps += __shfl_xor_sync(0xffffffffu, ps, o);
        l = l * sc + ps;
        m = mn;
        Ps[w][lane] = p0; Ps[w][lane+32] = p1;
        __syncwarp();

        uint64_t scp;
        asm("mov.b64 %0, {%1, %1};" : "=l"(scp) : "f"(sc));
        asm("mul.rn.f32x2 %0, %0, %1;" : "+l"(acc2) : "l"(scp));
        #pragma unroll
        for (int j = 0; j < 32; ++j) {
            uint64_t pv = *(const uint64_t*)&Ps[w][2*j];
            uint64_t vv = *(const uint64_t*)&Vt[lane][2*j];
            asm("fma.rn.f32x2 %0, %1, %2, %0;" : "+l"(acc2) : "l"(pv), "l"(vv));
        }
        __syncthreads();
    }
    float alo, ahi;
    asm("mov.b64 {%0, %1}, %2;" : "=f"(alo), "=f"(ahi) : "l"(acc2));
    O[((size_t)(b*LQV + q))*CCV + h*DHV + lane] = __float2bfloat16((alo + ahi) / l);
}

// ---------------- LayerNorm (optionally also emit bf16) ---------------------
template<bool BF>
__global__ __launch_bounds__(256) void ln_kernel(
    const float* __restrict__ x, const float* __restrict__ g,
    const float* __restrict__ b, float* __restrict__ y,
    __nv_bfloat16* __restrict__ ybf)
{
    const int row = blockIdx.x;
    const int t = threadIdx.x;
    float v = x[(size_t)row * 256 + t];
    float s = v, sq = v * v;
    #pragma unroll
    for (int o = 16; o > 0; o >>= 1) {
        s  += __shfl_xor_sync(0xffffffffu, s,  o);
        sq += __shfl_xor_sync(0xffffffffu, sq, o);
    }
    __shared__ float sh1[8], sh2[8];
    int wid = t >> 5, lane = t & 31;
    if (lane == 0) { sh1[wid] = s; sh2[wid] = sq; }
    __syncthreads();
    float S = 0.f, SQ = 0.f;
    #pragma unroll
    for (int i = 0; i < 8; ++i) { S += sh1[i]; SQ += sh2[i]; }
    float mean = S * (1.f/256.f);
    float var  = SQ * (1.f/256.f) - mean * mean;
    float r = (v - mean) * rsqrtf(var + 1e-5f) * g[t] + b[t];
    y[(size_t)row * 256 + t] = r;
    if (BF) ybf[(size_t)row * 256 + t] = __float2bfloat16(r);
}

// ---------------- attention-weight softmax over L*P=16 ----------------------
__global__ void awsm_kernel(const float* __restrict__ in, float* __restrict__ out) {
    int i = blockIdx.x * blockDim.x + threadIdx.x;
    if (i >= MQ * HHV) return;
    int bq = i >> 3, h = i & 7;
    const float* p = in + (size_t)bq * 128 + h * 16;
    float vals[16], mx = -1e30f;
    #pragma unroll
    for (int k = 0; k < 16; ++k) { vals[k] = p[k]; mx = fmaxf(mx, vals[k]); }
    float sum = 0.f;
    #pragma unroll
    for (int k = 0; k < 16; ++k) { vals[k] = __expf(vals[k] - mx); sum += vals[k]; }
    float inv = 1.f / sum;
    float* o = out + (size_t)bq * 128 + h * 16;
    #pragma unroll
    for (int k = 0; k < 16; ++k) o[k] = vals[k] * inv;
}

// ---------------- deformable sampling: warp per (b,q,h), bf16 out -----------
__global__ __launch_bounds__(256) void deform_kernel(
    const float* __restrict__ val, const float* __restrict__ ref,
    const float* __restrict__ offs, const float* __restrict__ aw,
    __nv_bfloat16* __restrict__ out)
{
    const int gw = (blockIdx.x * blockDim.x + threadIdx.x) >> 5;
    const int lane = threadIdx.x & 31;
    if (gw >= MQ * HHV) return;
    const int bq = gw >> 3, h = gw & 7;
    const int b = bq >> 10;

    const int starts[4] = {0, 16384, 20480, 21504};
    const int WL[4]     = {128, 64, 32, 16};

    const float* offp = offs + (size_t)bq * 256 + h * 32;
    const float* awp  = aw   + (size_t)bq * 128 + h * 16;
    const float* refp = ref  + (size_t)bq * 8;

    float acc = 0.f;
    #pragma unroll
    for (int l = 0; l < 4; ++l) {
        const int wl = WL[l];
        const float fwl = (float)wl;
        const float rx = refp[l*2+0], ry = refp[l*2+1];
        const int base_l = b * LSRCV + starts[l];
        #pragma unroll
        for (int p = 0; p < 4; ++p) {
            float ox = offp[l*8 + p*2 + 0];
            float oy = offp[l*8 + p*2 + 1];
            float a  = awp[l*4 + p];
            float x = (rx + ox / fwl) * fwl - 0.5f;
            float y = (ry + oy / fwl) * fwl - 0.5f;
            float x0f = floorf(x), y0f = floorf(y);
            int x0 = (int)x0f, y0 = (int)y0f;
            float wx1 = x - x0f, wx0 = 1.f - wx1;
            float wy1 = y - y0f, wy0 = 1.f - wy1;
            #pragma unroll
            for (int dy = 0; dy < 2; ++dy) {
                #pragma unroll
                for (int dx = 0; dx < 2; ++dx) {
                    int xi = x0 + dx, yi = y0 + dy;
                    if (xi >= 0 && xi < wl && yi >= 0 && yi < wl) {
                        float wgt = (dx ? wx1 : wx0) * (dy ? wy1 : wy0);
                        float vv = val[((size_t)(base_l + yi*wl + xi))*CCV + h*32 + lane];
                        acc += a * wgt * vv;
                    }
                }
            }
        }
    }
    out[(size_t)bq * 256 + h * 32 + lane] = __float2bfloat16(acc);
}

// ---------------- orchestration ---------------------------------------------
extern "C" void kernel_launch(void* const* d_in, const int* in_sizes, int n_in,
                              void* d_out, int out_size)
{
    const float* tgt   = (const float*)d_in[0];
    const float* qpos  = (const float*)d_in[1];
    const float* refp  = (const float*)d_in[2];
    const float* src   = (const float*)d_in[3];
    const float* in_w  = (const float*)d_in[4];
    const float* in_b  = (const float*)d_in[5];
    const float* sa_w  = (const float*)d_in[6];
    const float* sa_b  = (const float*)d_in[7];
    const float* off_w = (const float*)d_in[8];
    const float* off_b = (const float*)d_in[9];
    const float* aw_w  = (const float*)d_in[10];
    const float* aw_b  = (const float*)d_in[11];
    const float* val_w = (const float*)d_in[12];
    const float* val_b = (const float*)d_in[13];
    const float* co_w  = (const float*)d_in[14];
    const float* co_b  = (const float*)d_in[15];
    const float* ln1_g = (const float*)d_in[16];
    const float* ln1_b = (const float*)d_in[17];
    const float* ln2_g = (const float*)d_in[18];
    const float* ln2_b = (const float*)d_in[19];
    const float* ln3_g = (const float*)d_in[20];
    const float* ln3_b = (const float*)d_in[21];
    const float* f1_w  = (const float*)d_in[22];
    const float* f1_b  = (const float*)d_in[23];
    const float* f2_w  = (const float*)d_in[24];
    const float* f2_b  = (const float*)d_in[25];
    float* out = (float*)d_out;

    float *p_qkq, *p_v, *p_res, *p_tgta, *p_value, *p_off, *p_aw, *p_tgtb;
    cudaGetSymbolAddress((void**)&p_qkq,  g_qkq);
    cudaGetSymbolAddress((void**)&p_v,    g_v);
    cudaGetSymbolAddress((void**)&p_res,  g_res);
    cudaGetSymbolAddress((void**)&p_tgta, g_tgta);
    cudaGetSymbolAddress((void**)&p_value,g_value);
    cudaGetSymbolAddress((void**)&p_off,  g_off);
    cudaGetSymbolAddress((void**)&p_aw,   g_aw);
    cudaGetSymbolAddress((void**)&p_tgtb, g_tgtb);

    __nv_bfloat16 *q_qk, *q_tgt, *q_attn, *q_src, *q_q2, *q_samp, *q_tgtb, *q_hid;
    __nv_bfloat16 *w_in, *w_sa, *w_val, *w_off, *w_aw, *w_co, *w_f1, *w_f2;
    cudaGetSymbolAddress((void**)&q_qk,   b_qk);
    cudaGetSymbolAddress((void**)&q_tgt,  b_tgt);
    cudaGetSymbolAddress((void**)&q_attn, b_attn);
    cudaGetSymbolAddress((void**)&q_src,  b_src);
    cudaGetSymbolAddress((void**)&q_q2,   b_q2);
    cudaGetSymbolAddress((void**)&q_samp, b_samp);
    cudaGetSymbolAddress((void**)&q_tgtb, b_tgtb);
    cudaGetSymbolAddress((void**)&q_hid,  b_hid);
    cudaGetSymbolAddress((void**)&w_in,   b_inw);
    cudaGetSymbolAddress((void**)&w_sa,   b_saw);
    cudaGetSymbolAddress((void**)&w_val,  b_valw);
    cudaGetSymbolAddress((void**)&w_off,  b_offw);
    cudaGetSymbolAddress((void**)&w_aw,   b_aww);
    cudaGetSymbolAddress((void**)&w_co,   b_cow);
    cudaGetSymbolAddress((void**)&w_f1,   b_f1w);
    cudaGetSymbolAddress((void**)&w_f2,   b_f2w);

    const int NQ = MQ * CCV;   // 1048576

    // ---- fused convert: tgt, src, and all weights ----
    CvtArgs ca;
    const float* csrc[10] = {tgt, src, in_w, sa_w, val_w, off_w, aw_w, co_w, f1_w, f2_w};
    __nv_bfloat16* cdst[10] = {q_tgt, q_src, w_in, w_sa, w_val, w_off, w_aw, w_co, w_f1, w_f2};
    int cn[10] = {NQ, MS*CCV, 3*CCV*CCV, CCV*CCV, CCV*CCV, CCV*CCV, 128*CCV, CCV*CCV,
                  DFFV*CCV, CCV*DFFV};
    int acc4 = 0;
    for (int k = 0; k < 10; ++k) {
        ca.s[k] = csrc[k]; ca.d[k] = cdst[k];
        acc4 += cn[k] / 4; ca.end4[k] = acc4;
    }
    cvt_all<<<(acc4 + 255)/256, 256>>>(ca, acc4);

    // ---- self-attention ----
    add_bf_kernel<<<NQ/512, 256>>>(tgt, qpos, q_qk, NQ/2);
    gemmb<64,false,false,false><<<dim3(4,64), 256>>>(q_qk, w_in, in_b, nullptr, p_qkq, nullptr, MQ, 512, 256);
    gemmb<64,false,false,false><<<dim3(2,64), 256>>>(q_tgt, w_in + 512*256, in_b + 512, nullptr, p_v, nullptr, MQ, 256, 256);
    attn_kernel<<<dim3(32,128), 256>>>(p_qkq, p_qkq + 256, p_v, q_attn);
    gemmb<64,false,true ,false><<<dim3(2,64), 256>>>(q_attn, w_sa, sa_b, tgt, p_res, nullptr, MQ, 256, 256);
    ln_kernel<false><<<MQ, 256>>>(p_res, ln2_g, ln2_b, p_tgta, nullptr);

    // ---- deformable cross-attention ----
    gemmb<128,false,false,false><<<dim3(2,680), 256>>>(q_src, w_val, val_b, nullptr, p_value, nullptr, MS, 256, 256);
    add_bf_kernel<<<NQ/512, 256>>>(p_tgta, qpos, q_q2, NQ/2);
    gemmb<64,false,false,false><<<dim3(2,64), 256>>>(q_q2, w_off, off_b, nullptr, p_off, nullptr, MQ, 256, 256);
    gemmb<64,false,false,false><<<dim3(1,64), 256>>>(q_q2, w_aw,  aw_b,  nullptr, p_res, nullptr, MQ, 128, 256);
    awsm_kernel<<<128, 256>>>(p_res, p_aw);
    deform_kernel<<<4096, 256>>>(p_value, refp, p_off, p_aw, q_samp);
    gemmb<64,false,true ,false><<<dim3(2,64), 256>>>(q_samp, w_co, co_b, p_tgta, p_res, nullptr, MQ, 256, 256);
    ln_kernel<true ><<<MQ, 256>>>(p_res, ln1_g, ln1_b, p_tgtb, q_tgtb);

    // ---- FFN ----
    gemmb<128,true ,false,true ><<<dim3(8,32), 256>>>(q_tgtb, w_f1, f1_b, nullptr, nullptr, q_hid, MQ, 1024, 256);
    gemmb<64,false,true ,false><<<dim3(2,64), 256>>>(q_hid, w_f2, f2_b, p_tgtb, p_res, nullptr, MQ, 256, 1024);
    ln_kernel<false><<<MQ, 256>>>(p_res, ln3_g, ln3_b, out, nullptr);
}

// round 11
// speedup vs baseline: 4.8421x; 2.5962x over previous
#include <cuda_runtime.h>
#include <cuda_bf16.h>
#include <math.h>
#include <stdint.h>

#define BB   4
#define LQV  1024
#define CCV  256
#define HHV  8
#define DHV  32
#define DFFV 1024
#define LSRCV 21760
#define MQ (BB*LQV)     // 4096
#define MS (BB*LSRCV)   // 87040

// ---------------- fp32 scratch ----------------------------------------------
__device__ float g_res [MQ*CCV];
__device__ float g_tgta[MQ*CCV];
__device__ float g_value[(size_t)MS*CCV];
__device__ float g_offaw[MQ*384];
__device__ float g_aw  [MQ*128];
__device__ float g_tgtb[MQ*CCV];

// ---------------- bf16 scratch ----------------------------------------------
__device__ __nv_bfloat16 b_qk  [MQ*CCV];
__device__ __nv_bfloat16 b_tgt [MQ*CCV];
__device__ __nv_bfloat16 b_qkv [MQ*768];
__device__ __nv_bfloat16 b_attn[MQ*CCV];
__device__ __nv_bfloat16 b_src [(size_t)MS*CCV];
__device__ __nv_bfloat16 b_q2  [MQ*CCV];
__device__ __nv_bfloat16 b_samp[MQ*CCV];
__device__ __nv_bfloat16 b_tgtb[MQ*CCV];
__device__ __nv_bfloat16 b_hid [MQ*DFFV];
__device__ __nv_bfloat16 b_inw [3*CCV*CCV];
__device__ __nv_bfloat16 b_saw [CCV*CCV];
__device__ __nv_bfloat16 b_valw[CCV*CCV];
__device__ __nv_bfloat16 b_offaww[384*CCV];
__device__ __nv_bfloat16 b_cow [CCV*CCV];
__device__ __nv_bfloat16 b_f1w [DFFV*CCV];
__device__ __nv_bfloat16 b_f2w [CCV*DFFV];

__device__ __forceinline__ uint32_t smem_u32(const void* p) {
    uint32_t a;
    asm("{ .reg .u64 t; cvta.to.shared.u64 t, %1; cvt.u32.u64 %0, t; }"
        : "=r"(a) : "l"(p));
    return a;
}

__device__ __forceinline__ void mma_bf16(
    float* c, uint32_t a0, uint32_t a1, uint32_t a2, uint32_t a3,
    uint32_t b0, uint32_t b1)
{
    asm volatile(
        "mma.sync.aligned.m16n8k16.row.col.f32.bf16.bf16.f32 "
        "{%0,%1,%2,%3},{%4,%5,%6,%7},{%8,%9},{%0,%1,%2,%3};"
        : "+f"(c[0]), "+f"(c[1]), "+f"(c[2]), "+f"(c[3])
        : "r"(a0), "r"(a1), "r"(a2), "r"(a3), "r"(b0), "r"(b1));
}

__device__ __forceinline__ uint32_t packbf(float a, float b) {
    __nv_bfloat162 h = __floats2bfloat162_rn(a, b);
    return *reinterpret_cast<uint32_t*>(&h);
}

// ---------------- fused fp32 -> bf16 convert (10 segments) -------------------
struct CvtArgs {
    const float* s[10];
    __nv_bfloat16* d[10];
    int end4[10];
};

__global__ void cvt_all(CvtArgs a, int total4) {
    int i = blockIdx.x * blockDim.x + threadIdx.x;
    if (i >= total4) return;
    int seg = 0;
    #pragma unroll
    for (int k = 0; k < 9; ++k) if (i >= a.end4[k]) seg = k + 1;
    int base = seg ? a.end4[seg - 1] : 0;
    int li = i - base;
    float4 v = ((const float4*)a.s[seg])[li];
    ((uint2*)a.d[seg])[li] = make_uint2(packbf(v.x, v.y), packbf(v.z, v.w));
}

// ---------------- add -> bf16 -----------------------------------------------
__global__ void add_bf_kernel(const float* __restrict__ a, const float* __restrict__ b,
                              __nv_bfloat16* __restrict__ o, int n2) {
    int i = blockIdx.x * blockDim.x + threadIdx.x;
    if (i >= n2) return;
    float2 va = ((const float2*)a)[i];
    float2 vb = ((const float2*)b)[i];
    ((uint32_t*)o)[i] = packbf(va.x + vb.x, va.y + vb.y);
}

// ---------------- bf16 mma GEMM, 3-stage cp.async, fused A/bias --------------
// C = A(MxK)bf16 * W(NxK)bf16^T + bias [+resid][relu].
// Blocks with bn >= an_split read A2; bias cols >= b_split read bias2.
#define RSTRIDE 80

template<int BM, bool RELU, bool RESID, bool OUTBF>
__global__ __launch_bounds__(256, (BM == 64) ? 3 : 2) void gemmb(
    const __nv_bfloat16* __restrict__ A, const __nv_bfloat16* __restrict__ A2,
    int an_split,
    const __nv_bfloat16* __restrict__ W,
    const float* __restrict__ bias, const float* __restrict__ bias2, int b_split,
    const float* __restrict__ resid,
    float* __restrict__ Cf, __nv_bfloat16* __restrict__ Cb, int M, int N, int K)
{
    constexpr int MI = BM / 32;
    constexpr int CH = (BM + 128) / 64;
    __shared__ __align__(16) char sm[3][(BM + 128) * RSTRIDE];

    const int tid  = threadIdx.x;
    const int wid  = tid >> 5;
    const int lane = tid & 31;
    const int bm = blockIdx.y * BM;
    const int bn = blockIdx.x * 128;
    const int wm = (wid & 1) * (BM / 2);
    const int wn = (wid >> 1) * 32;

    const __nv_bfloat16* Ause = (bn >= an_split) ? A2 : A;

    float acc[MI][4][4] = {};
    const int NS = K >> 5;

    auto stage_load = [&](int buf, int slab) {
        const int kt = slab * 32;
        char* base = sm[buf];
        #pragma unroll
        for (int u = 0; u < CH; ++u) {
            int idx = tid + u * 256;
            bool isB = idx >= BM * 4;
            int row = isB ? ((idx - BM * 4) >> 2) : (idx >> 2);
            int col = idx & 3;
            const void* g = isB ? (const void*)(W + (size_t)(bn + row) * K + kt + col * 8)
                                : (const void*)(Ause + (size_t)(bm + row) * K + kt + col * 8);
            uint32_t d = smem_u32(base + (isB ? BM * RSTRIDE : 0) + row * RSTRIDE + col * 16);
            asm volatile("cp.async.cg.shared.global [%0], [%1], 16;" :: "r"(d), "l"(g));
        }
        asm volatile("cp.async.commit_group;");
    };

    stage_load(0, 0);
    if (NS > 1) stage_load(1, 1);
    if (NS > 2) stage_load(2, 2);

    for (int s = 0; s < NS; ++s) {
        int pend = NS - s - 1; if (pend > 2) pend = 2;
        if (pend == 2)      asm volatile("cp.async.wait_group 2;");
        else if (pend == 1) asm volatile("cp.async.wait_group 1;");
        else                asm volatile("cp.async.wait_group 0;");
        __syncthreads();

        char* sA = sm[s % 3];
        char* sB = sm[s % 3] + BM * RSTRIDE;

        #pragma unroll
        for (int h = 0; h < 2; ++h) {
            const int kb = h * 32 + (lane >> 4) * 16;
            uint32_t a[MI][4], b[4][2];
            #pragma unroll
            for (int i = 0; i < MI; ++i) {
                uint32_t addr = smem_u32(sA + (wm + i*16 + (lane & 15)) * RSTRIDE + kb);
                asm volatile("ldmatrix.sync.aligned.m8n8.x4.shared.b16 {%0,%1,%2,%3}, [%4];"
                    : "=r"(a[i][0]), "=r"(a[i][1]), "=r"(a[i][2]), "=r"(a[i][3]) : "r"(addr));
            }
            #pragma unroll
            for (int jj = 0; jj < 2; ++jj) {
                uint32_t r0, r1, r2, r3;
                uint32_t addr = smem_u32(sB + (wn + jj*16 + (lane & 15)) * RSTRIDE + kb);
                asm volatile("ldmatrix.sync.aligned.m8n8.x4.shared.b16 {%0,%1,%2,%3}, [%4];"
                    : "=r"(r0), "=r"(r1), "=r"(r2), "=r"(r3) : "r"(addr));
                b[jj*2  ][0] = r0; b[jj*2  ][1] = r2;
                b[jj*2+1][0] = r1; b[jj*2+1][1] = r3;
            }
            #pragma unroll
            for (int i = 0; i < MI; ++i)
                #pragma unroll
                for (int j = 0; j < 4; ++j)
                    mma_bf16(acc[i][j], a[i][0], a[i][1], a[i][2], a[i][3],
                             b[j][0], b[j][1]);
        }
        __syncthreads();
        if (s + 3 < NS) stage_load(s % 3, s + 3);
    }

    #pragma unroll
    for (int i = 0; i < MI; ++i) {
        const int rbase = bm + wm + i*16 + (lane >> 2);
        #pragma unroll
        for (int rr = 0; rr < 2; ++rr) {
            const int r = rbase + rr * 8;
            #pragma unroll
            for (int j = 0; j < 4; ++j) {
                const int cc = bn + wn + j*8 + (lane & 3) * 2;
                float b0 = (cc < b_split) ? bias[cc]   : bias2[cc - b_split];
                float b1 = (cc + 1 < b_split) ? bias[cc+1] : bias2[cc + 1 - b_split];
                float v0 = acc[i][j][rr*2+0] + b0;
                float v1 = acc[i][j][rr*2+1] + b1;
                if (RESID) {
                    float2 rv = *(const float2*)&resid[(size_t)r * N + cc];
                    v0 += rv.x; v1 += rv.y;
                }
                if (RELU) { v0 = fmaxf(v0, 0.f); v1 = fmaxf(v1, 0.f); }
                if (OUTBF) {
                    uint32_t bv = packbf(v0, v1);
                    *(uint32_t*)&Cb[(size_t)r * N + cc] = bv;
                } else {
                    *(float2*)&Cf[(size_t)r * N + cc] = make_float2(v0, v1);
                }
            }
        }
    }
}

// ---------------- mma flash attention ----------------------------------------
// QKV bf16 [token][768]: Q 0..255, K 256..511, V 512..767. 64 q/block, 4 warps.
__global__ __launch_bounds__(128) void attn_mma(
    const __nv_bfloat16* __restrict__ QKV, __nv_bfloat16* __restrict__ O)
{
    __shared__ __align__(16) char s_q[64*80];
    __shared__ __align__(16) char s_k[2][64*80];
    __shared__ __align__(16) char s_v[2][64*80];

    const int bh = blockIdx.x;
    const int b = bh >> 3, h = bh & 7;
    const int w = threadIdx.x >> 5;
    const int lane = threadIdx.x & 31;
    const int tid = threadIdx.x;
    const int q0 = blockIdx.y * 64;
    const __nv_bfloat16* base = QKV + (size_t)(b * LQV) * 768;

    // Q tile: 64 rows x 32 bf16 (4 chunks of 16B per row)
    #pragma unroll
    for (int u = 0; u < 2; ++u) {
        int idx = tid * 2 + u;
        int r = idx >> 2, c = idx & 3;
        const void* g = base + (size_t)(q0 + r) * 768 + h * 32 + c * 8;
        uint32_t d = smem_u32(s_q + r * 80 + c * 16);
        asm volatile("cp.async.cg.shared.global [%0], [%1], 16;" :: "r"(d), "l"(g));
    }
    asm volatile("cp.async.commit_group;");

    auto load_kv = [&](int buf, int kt) {
        #pragma unroll
        for (int u = 0; u < 2; ++u) {
            int idx = tid * 2 + u;
            int r = idx >> 2, c = idx & 3;
            const void* gk = base + (size_t)(kt + r) * 768 + 256 + h * 32 + c * 8;
            const void* gv = base + (size_t)(kt + r) * 768 + 512 + h * 32 + c * 8;
            uint32_t dk = smem_u32(s_k[buf] + r * 80 + c * 16);
            uint32_t dv = smem_u32(s_v[buf] + r * 80 + c * 16);
            asm volatile("cp.async.cg.shared.global [%0], [%1], 16;" :: "r"(dk), "l"(gk));
            asm volatile("cp.async.cg.shared.global [%0], [%1], 16;" :: "r"(dv), "l"(gv));
        }
        asm volatile("cp.async.commit_group;");
    };
    load_kv(0, 0);
    load_kv(1, 64);

    // Q + kv0 ready
    asm volatile("cp.async.wait_group 1;");
    __syncthreads();

    uint32_t aQ[2][4];
    #pragma unroll
    for (int ks = 0; ks < 2; ++ks) {
        uint32_t addr = smem_u32(s_q + (w*16 + (lane & 15)) * 80 + ks * 32 + (lane >> 4) * 16);
        asm volatile("ldmatrix.sync.aligned.m8n8.x4.shared.b16 {%0,%1,%2,%3}, [%4];"
            : "=r"(aQ[ks][0]), "=r"(aQ[ks][1]), "=r"(aQ[ks][2]), "=r"(aQ[ks][3]) : "r"(addr));
    }

    const float scale = 0.17677669529663687f;
    float m0 = -1e30f, m1 = -1e30f, l0 = 0.f, l1 = 0.f;
    float oacc[4][4] = {};

    for (int it = 0; it < 16; ++it) {
        if (it) {
            if (it < 15) asm volatile("cp.async.wait_group 1;");
            else         asm volatile("cp.async.wait_group 0;");
            __syncthreads();
        }
        char* sk = s_k[it & 1];
        char* sv = s_v[it & 1];

        // S = Q * K^T  (16q x 64k per warp)
        float sacc[8][4] = {};
        #pragma unroll
        for (int ks = 0; ks < 2; ++ks) {
            const int kb = ks * 32 + (lane >> 4) * 16;
            #pragma unroll
            for (int jj = 0; jj < 4; ++jj) {
                uint32_t r0, r1, r2, r3;
                uint32_t addr = smem_u32(sk + (jj*16 + (lane & 15)) * 80 + kb);
                asm volatile("ldmatrix.sync.aligned.m8n8.x4.shared.b16 {%0,%1,%2,%3}, [%4];"
                    : "=r"(r0), "=r"(r1), "=r"(r2), "=r"(r3) : "r"(addr));
                mma_bf16(sacc[jj*2],   aQ[ks][0], aQ[ks][1], aQ[ks][2], aQ[ks][3], r0, r2);
                mma_bf16(sacc[jj*2+1], aQ[ks][0], aQ[ks][1], aQ[ks][2], aQ[ks][3], r1, r3);
            }
        }

        // V fragments via ldmatrix.trans (B[n=d][k=key] from V[key][d])
        uint32_t bV[4][4][2];
        #pragma unroll
        for (int dj = 0; dj < 4; ++dj)
            #pragma unroll
            for (int kp = 0; kp < 2; ++kp) {
                uint32_t r0, r1, r2, r3;
                uint32_t addr = smem_u32(sv + (kp*32 + lane) * 80 + dj * 16);
                asm volatile("ldmatrix.sync.aligned.m8n8.x4.trans.shared.b16 {%0,%1,%2,%3}, [%4];"
                    : "=r"(r0), "=r"(r1), "=r"(r2), "=r"(r3) : "r"(addr));
                bV[dj][kp*2  ][0] = r0; bV[dj][kp*2  ][1] = r1;
                bV[dj][kp*2+1][0] = r2; bV[dj][kp*2+1][1] = r3;
            }

        // online softmax on fragments: rows rg (c0,c1) and rg+8 (c2,c3)
        float mx0 = -1e30f, mx1 = -1e30f;
        #pragma unroll
        for (int j = 0; j < 8; ++j) {
            sacc[j][0] *= scale; sacc[j][1] *= scale;
            sacc[j][2] *= scale; sacc[j][3] *= scale;
            mx0 = fmaxf(mx0, fmaxf(sacc[j][0], sacc[j][1]));
            mx1 = fmaxf(mx1, fmaxf(sacc[j][2], sacc[j][3]));
        }
        mx0 = fmaxf(mx0, __shfl_xor_sync(0xffffffffu, mx0, 1));
        mx0 = fmaxf(mx0, __shfl_xor_sync(0xffffffffu, mx0, 2));
        mx1 = fmaxf(mx1, __shfl_xor_sync(0xffffffffu, mx1, 1));
        mx1 = fmaxf(mx1, __shfl_xor_sync(0xffffffffu, mx1, 2));
        float m0n = fmaxf(m0, mx0), m1n = fmaxf(m1, mx1);
        float f0 = __expf(m0 - m0n), f1 = __expf(m1 - m1n);
        float s0 = 0.f, s1 = 0.f;
        #pragma unroll
        for (int j = 0; j < 8; ++j) {
            sacc[j][0] = __expf(sacc[j][0] - m0n);
            sacc[j][1] = __expf(sacc[j][1] - m0n);
            sacc[j][2] = __expf(sacc[j][2] - m1n);
            sacc[j][3] = __expf(sacc[j][3] - m1n);
            s0 += sacc[j][0] + sacc[j][1];
            s1 += sacc[j][2] + sacc[j][3];
        }
        s0 += __shfl_xor_sync(0xffffffffu, s0, 1);
        s0 += __shfl_xor_sync(0xffffffffu, s0, 2);
        s1 += __shfl_xor_sync(0xffffffffu, s1, 1);
        s1 += __shfl_xor_sync(0xffffffffu, s1, 2);
        l0 = l0 * f0 + s0; l1 = l1 * f1 + s1;
        m0 = m0n; m1 = m1n;
        #pragma unroll
        for (int dj = 0; dj < 4; ++dj) {
            oacc[dj][0] *= f0; oacc[dj][1] *= f0;
            oacc[dj][2] *= f1; oacc[dj][3] *= f1;
        }

        // P -> bf16 A fragments, PV mma
        #pragma unroll
        for (int kk = 0; kk < 4; ++kk) {
            uint32_t a0 = packbf(sacc[2*kk][0],   sacc[2*kk][1]);
            uint32_t a1 = packbf(sacc[2*kk][2],   sacc[2*kk][3]);
            uint32_t a2 = packbf(sacc[2*kk+1][0], sacc[2*kk+1][1]);
            uint32_t a3 = packbf(sacc[2*kk+1][2], sacc[2*kk+1][3]);
            #pragma unroll
            for (int dj = 0; dj < 4; ++dj)
                mma_bf16(oacc[dj], a0, a1, a2, a3, bV[dj][kk][0], bV[dj][kk][1]);
        }

        __syncthreads();
        if (it + 2 < 16) load_kv(it & 1, (it + 2) * 64);
    }

    const int rg = lane >> 2, cg = lane & 3;
    const int row0 = b * LQV + q0 + w * 16 + rg;
    const float il0 = 1.f / l0, il1 = 1.f / l1;
    #pragma unroll
    for (int dj = 0; dj < 4; ++dj) {
        int col = h * 32 + dj * 8 + cg * 2;
        *(uint32_t*)&O[(size_t)row0 * 256 + col] =
            packbf(oacc[dj][0] * il0, oacc[dj][1] * il0);
        *(uint32_t*)&O[(size_t)(row0 + 8) * 256 + col] =
            packbf(oacc[dj][2] * il1, oacc[dj][3] * il1);
    }
}

// ---------------- LayerNorm (optionally also emit bf16) ---------------------
template<bool BF>
__global__ __launch_bounds__(256) void ln_kernel(
    const float* __restrict__ x, const float* __restrict__ g,
    const float* __restrict__ b, float* __restrict__ y,
    __nv_bfloat16* __restrict__ ybf)
{
    const int row = blockIdx.x;
    const int t = threadIdx.x;
    float v = x[(size_t)row * 256 + t];
    float s = v, sq = v * v;
    #pragma unroll
    for (int o = 16; o > 0; o >>= 1) {
        s  += __shfl_xor_sync(0xffffffffu, s,  o);
        sq += __shfl_xor_sync(0xffffffffu, sq, o);
    }
    __shared__ float sh1[8], sh2[8];
    int wid = t >> 5, lane = t & 31;
    if (lane == 0) { sh1[wid] = s; sh2[wid] = sq; }
    __syncthreads();
    float S = 0.f, SQ = 0.f;
    #pragma unroll
    for (int i = 0; i < 8; ++i) { S += sh1[i]; SQ += sh2[i]; }
    float mean = S * (1.f/256.f);
    float var  = SQ * (1.f/256.f) - mean * mean;
    float r = (v - mean) * rsqrtf(var + 1e-5f) * g[t] + b[t];
    y[(size_t)row * 256 + t] = r;
    if (BF) ybf[(size_t)row * 256 + t] = __float2bfloat16(r);
}

// ---------------- attention-weight softmax (in stride 384, offset 256) -------
__global__ void awsm_kernel(const float* __restrict__ in, float* __restrict__ out) {
    int i = blockIdx.x * blockDim.x + threadIdx.x;
    if (i >= MQ * HHV) return;
    int bq = i >> 3, h = i & 7;
    const float* p = in + (size_t)bq * 384 + 256 + h * 16;
    float vals[16], mx = -1e30f;
    #pragma unroll
    for (int k = 0; k < 16; ++k) { vals[k] = p[k]; mx = fmaxf(mx, vals[k]); }
    float sum = 0.f;
    #pragma unroll
    for (int k = 0; k < 16; ++k) { vals[k] = __expf(vals[k] - mx); sum += vals[k]; }
    float inv = 1.f / sum;
    float* o = out + (size_t)bq * 128 + h * 16;
    #pragma unroll
    for (int k = 0; k < 16; ++k) o[k] = vals[k] * inv;
}

// ---------------- deformable sampling (offsets stride 384) -------------------
__global__ __launch_bounds__(256) void deform_kernel(
    const float* __restrict__ val, const float* __restrict__ ref,
    const float* __restrict__ offs, const float* __restrict__ aw,
    __nv_bfloat16* __restrict__ out)
{
    const int gw = (blockIdx.x * blockDim.x + threadIdx.x) >> 5;
    const int lane = threadIdx.x & 31;
    if (gw >= MQ * HHV) return;
    const int bq = gw >> 3, h = gw & 7;
    const int b = bq >> 10;

    const int starts[4] = {0, 16384, 20480, 21504};
    const int WL[4]     = {128, 64, 32, 16};

    const float* offp = offs + (size_t)bq * 384 + h * 32;
    const float* awp  = aw   + (size_t)bq * 128 + h * 16;
    const float* refp = ref  + (size_t)bq * 8;

    float acc = 0.f;
    #pragma unroll
    for (int l = 0; l < 4; ++l) {
        const int wl = WL[l];
        const float fwl = (float)wl;
        const float rx = refp[l*2+0], ry = refp[l*2+1];
        const int base_l = b * LSRCV + starts[l];
        #pragma unroll
        for (int p = 0; p < 4; ++p) {
            float ox = offp[l*8 + p*2 + 0];
            float oy = offp[l*8 + p*2 + 1];
            float a  = awp[l*4 + p];
            float x = (rx + ox / fwl) * fwl - 0.5f;
            float y = (ry + oy / fwl) * fwl - 0.5f;
            float x0f = floorf(x), y0f = floorf(y);
            int x0 = (int)x0f, y0 = (int)y0f;
            float wx1 = x - x0f, wx0 = 1.f - wx1;
            float wy1 = y - y0f, wy0 = 1.f - wy1;
            #pragma unroll
            for (int dy = 0; dy < 2; ++dy) {
                #pragma unroll
                for (int dx = 0; dx < 2; ++dx) {
                    int xi = x0 + dx, yi = y0 + dy;
                    if (xi >= 0 && xi < wl && yi >= 0 && yi < wl) {
                        float wgt = (dx ? wx1 : wx0) * (dy ? wy1 : wy0);
                        float vv = val[((size_t)(base_l + yi*wl + xi))*CCV + h*32 + lane];
                        acc += a * wgt * vv;
                    }
                }
            }
        }
    }
    out[(size_t)bq * 256 + h * 32 + lane] = __float2bfloat16(acc);
}

// ---------------- orchestration ---------------------------------------------
extern "C" void kernel_launch(void* const* d_in, const int* in_sizes, int n_in,
                              void* d_out, int out_size)
{
    const float* tgt   = (const float*)d_in[0];
    const float* qpos  = (const float*)d_in[1];
    const float* refp  = (const float*)d_in[2];
    const float* src   = (const float*)d_in[3];
    const float* in_w  = (const float*)d_in[4];
    const float* in_b  = (const float*)d_in[5];
    const float* sa_w  = (const float*)d_in[6];
    const float* sa_b  = (const float*)d_in[7];
    const float* off_w = (const float*)d_in[8];
    const float* off_b = (const float*)d_in[9];
    const float* aw_w  = (const float*)d_in[10];
    const float* aw_b  = (const float*)d_in[11];
    const float* val_w = (const float*)d_in[12];
    const float* val_b = (const float*)d_in[13];
    const float* co_w  = (const float*)d_in[14];
    const float* co_b  = (const float*)d_in[15];
    const float* ln1_g = (const float*)d_in[16];
    const float* ln1_b = (const float*)d_in[17];
    const float* ln2_g = (const float*)d_in[18];
    const float* ln2_b = (const float*)d_in[19];
    const float* ln3_g = (const float*)d_in[20];
    const float* ln3_b = (const float*)d_in[21];
    const float* f1_w  = (const float*)d_in[22];
    const float* f1_b  = (const float*)d_in[23];
    const float* f2_w  = (const float*)d_in[24];
    const float* f2_b  = (const float*)d_in[25];
    float* out = (float*)d_out;

    float *p_res, *p_tgta, *p_value, *p_offaw, *p_aw, *p_tgtb;
    cudaGetSymbolAddress((void**)&p_res,  g_res);
    cudaGetSymbolAddress((void**)&p_tgta, g_tgta);
    cudaGetSymbolAddress((void**)&p_value,g_value);
    cudaGetSymbolAddress((void**)&p_offaw,g_offaw);
    cudaGetSymbolAddress((void**)&p_aw,   g_aw);
    cudaGetSymbolAddress((void**)&p_tgtb, g_tgtb);

    __nv_bfloat16 *q_qk, *q_tgt, *q_qkv, *q_attn, *q_src, *q_q2, *q_samp, *q_tgtb, *q_hid;
    __nv_bfloat16 *w_in, *w_sa, *w_val, *w_offaw, *w_co, *w_f1, *w_f2;
    cudaGetSymbolAddress((void**)&q_qk,   b_qk);
    cudaGetSymbolAddress((void**)&q_tgt,  b_tgt);
    cudaGetSymbolAddress((void**)&q_qkv,  b_qkv);
    cudaGetSymbolAddress((void**)&q_attn, b_attn);
    cudaGetSymbolAddress((void**)&q_src,  b_src);
    cudaGetSymbolAddress((void**)&q_q2,   b_q2);
    cudaGetSymbolAddress((void**)&q_samp, b_samp);
    cudaGetSymbolAddress((void**)&q_tgtb, b_tgtb);
    cudaGetSymbolAddress((void**)&q_hid,  b_hid);
    cudaGetSymbolAddress((void**)&w_in,   b_inw);
    cudaGetSymbolAddress((void**)&w_sa,   b_saw);
    cudaGetSymbolAddress((void**)&w_val,  b_valw);
    cudaGetSymbolAddress((void**)&w_offaw,b_offaww);
    cudaGetSymbolAddress((void**)&w_co,   b_cow);
    cudaGetSymbolAddress((void**)&w_f1,   b_f1w);
    cudaGetSymbolAddress((void**)&w_f2,   b_f2w);

    const int NQ = MQ * CCV;
    const int BIG = 1 << 30;

    CvtArgs ca;
    const float* csrc[10] = {tgt, src, in_w, sa_w, val_w, off_w, aw_w, co_w, f1_w, f2_w};
    __nv_bfloat16* cdst[10] = {q_tgt, q_src, w_in, w_sa, w_val,
                               w_offaw, w_offaw + 256*256, w_co, w_f1, w_f2};
    int cn[10] = {NQ, MS*CCV, 3*CCV*CCV, CCV*CCV, CCV*CCV, CCV*CCV, 128*CCV, CCV*CCV,
                  DFFV*CCV, CCV*DFFV};
    int acc4 = 0;
    for (int k = 0; k < 10; ++k) {
        ca.s[k] = csrc[k]; ca.d[k] = cdst[k];
        acc4 += cn[k] / 4; ca.end4[k] = acc4;
    }
    cvt_all<<<(acc4 + 255)/256, 256>>>(ca, acc4);

    // ---- self-attention ----
    add_bf_kernel<<<NQ/512, 256>>>(tgt, qpos, q_qk, NQ/2);
    gemmb<64,false,false,true ><<<dim3(6,64), 256>>>(q_qk, q_tgt, 512, w_in,
        in_b, nullptr, BIG, nullptr, nullptr, q_qkv, MQ, 768, 256);
    attn_mma<<<dim3(32,16), 128>>>(q_qkv, q_attn);
    gemmb<64,false,true ,false><<<dim3(2,64), 256>>>(q_attn, q_attn, BIG, w_sa,
        sa_b, nullptr, BIG, tgt, p_res, nullptr, MQ, 256, 256);
    ln_kernel<false><<<MQ, 256>>>(p_res, ln2_g, ln2_b, p_tgta, nullptr);

    // ---- deformable cross-attention ----
    gemmb<128,false,false,false><<<dim3(2,680), 256>>>(q_src, q_src, BIG, w_val,
        val_b, nullptr, BIG, nullptr, p_value, nullptr, MS, 256, 256);
    add_bf_kernel<<<NQ/512, 256>>>(p_tgta, qpos, q_q2, NQ/2);
    gemmb<64,false,false,false><<<dim3(3,64), 256>>>(q_q2, q_q2, BIG, w_offaw,
        off_b, aw_b, 256, nullptr, p_offaw, nullptr, MQ, 384, 256);
    awsm_kernel<<<128, 256>>>(p_offaw, p_aw);
    deform_kernel<<<4096, 256>>>(p_value, refp, p_offaw, p_aw, q_samp);
    gemmb<64,false,true ,false><<<dim3(2,64), 256>>>(q_samp, q_samp, BIG, w_co,
        co_b, nullptr, BIG, p_tgta, p_res, nullptr, MQ, 256, 256);
    ln_kernel<true ><<<MQ, 256>>>(p_res, ln1_g, ln1_b, p_tgtb, q_tgtb);

    // ---- FFN ----
    gemmb<128,true ,false,true ><<<dim3(8,32), 256>>>(q_tgtb, q_tgtb, BIG, w_f1,
        f1_b, nullptr, BIG, nullptr, nullptr, q_hid, MQ, 1024, 256);
    gemmb<64,false,true ,false><<<dim3(2,64), 256>>>(q_hid, q_hid, BIG, w_f2,
        f2_b, nullptr, BIG, p_tgtb, p_res, nullptr, MQ, 256, 1024);
    ln_kernel<false><<<MQ, 256>>>(p_res, ln3_g, ln3_b, out, nullptr);
}